// round 15
// baseline (speedup 1.0000x reference)
#include <cuda_runtime.h>
#include <cstdint>

#define NN 100000
#define NE 1600000
#define NG 512
#define FD 100
#define FD2 200
#define OUTSZ (NG*2 + NG*200)

// ---------------- scratch (device globals; no allocation allowed) ----------------
__device__ float g_m [NN*FD];
__device__ float g_xd[NN*FD];
__device__ float g_out[NN*FD];    // agg output (GEMM1 input)
__device__ float g_hh[NN*FD2];    // MLP hidden (GEMM2 input)
__device__ float g_h [NN*FD];     // conv output
__device__ int   g_src[NE];
__device__ int   g_dst[NE];
__device__ int   g_col[NE];
__device__ int   g_rowptr[NN+1];
__device__ int   g_cursor[NN];
__device__ int   g_counts[NN];
__device__ int   g_batch[NN];
__device__ int   g_bsums[128];
__device__ int   g_boffs[128];
__device__ int   g_gcnt[NG];
__device__ int   g_grow[NG+1];
__device__ int   g_gcur[NG];
__device__ int   g_glist[NN];
__device__ int   g_is64;

// ================= f32x2 helpers (PTX ISA 8.6+, sm_100 family incl. sm_103) =================
#define FMA2(acc, a, b) \
    asm("fma.rn.f32x2 %0, %1, %2, %0;" : "+l"(acc) : "l"(a), "l"(b))
#define PK2(d, x) \
    asm("mov.b64 %0, {%1, %1};" : "=l"(d) : "f"(x))
#define UPK2(lo, hi, v) \
    asm("mov.b64 {%0, %1}, %2;" : "=f"(lo), "=f"(hi) : "l"(v))

// online softmax update, ONE exp per call: e = exp(-|v-mx|)
__device__ __forceinline__ void onl(float v, float& mx, float& d, float& n) {
    float t = v - mx;
    float e = __expf(-fabsf(t));
    if (t <= 0.f) {
        d += e;
        n += e * v;
    } else {
        d = d * e + 1.f;
        n = n * e + v;
        mx = v;
    }
}

// ---------------- dtype sniff ----------------
__global__ void detect_kernel(const unsigned long long* __restrict__ ei) {
    __shared__ int found;
    if (threadIdx.x == 0) found = 0;
    __syncthreads();
    unsigned long long v = ei[threadIdx.x];
    if ((v >> 32) != 0ULL) found = 1;
    __syncthreads();
    if (threadIdx.x == 0) g_is64 = found ? 0 : 1;
}

__global__ void prep_kernel(const void* __restrict__ ei, const void* __restrict__ bt,
                            float* __restrict__ out) {
    int i = blockIdx.x * blockDim.x + threadIdx.x;
    int is64 = g_is64;
    if (i < NE) {
        if (is64) {
            const long long* e = (const long long*)ei;
            g_src[i] = (int)e[i];
            g_dst[i] = (int)e[NE + i];
        } else {
            const int* e = (const int*)ei;
            g_src[i] = e[i];
            g_dst[i] = e[NE + i];
        }
    }
    if (i < NN) {
        if (is64) g_batch[i] = (int)((const long long*)bt)[i];
        else      g_batch[i] = ((const int*)bt)[i];
        g_counts[i] = 0;
    }
    if (i < NG)    g_gcnt[i] = 0;
    if (i < OUTSZ) out[i] = 0.0f;
}

__global__ void hist_kernel() {
    int i = blockIdx.x * blockDim.x + threadIdx.x;
    if (i < NE) atomicAdd(&g_counts[g_dst[i]], 1);
    if (i < NN) atomicAdd(&g_gcnt[g_batch[i]], 1);
}

__global__ void scan_block_kernel() {
    __shared__ int sh[1024];
    int t = threadIdx.x;
    int i = blockIdx.x * 1024 + t;
    int v = (i < NN) ? g_counts[i] : 0;
    sh[t] = v;
    __syncthreads();
    for (int off = 1; off < 1024; off <<= 1) {
        int tmp = (t >= off) ? sh[t - off] : 0;
        __syncthreads();
        sh[t] += tmp;
        __syncthreads();
    }
    if (i < NN) g_rowptr[i] = sh[t] - v;
    if (t == 1023) g_bsums[blockIdx.x] = sh[1023];
}

__global__ void scan_misc_kernel(int nb) {
    __shared__ int sg[NG];
    int t = threadIdx.x;
    if (blockIdx.x == 0) {
        if (t == 0) {
            int run = 0;
            for (int i = 0; i < nb; i++) { g_boffs[i] = run; run += g_bsums[i]; }
            g_rowptr[NN] = run;
        }
    } else {
        int v = (t < NG) ? g_gcnt[t] : 0;
        if (t < NG) sg[t] = v;
        __syncthreads();
        for (int off = 1; off < NG; off <<= 1) {
            int tmp = (t < NG && t >= off) ? sg[t - off] : 0;
            __syncthreads();
            if (t < NG) sg[t] += tmp;
            __syncthreads();
        }
        if (t < NG) { g_grow[t] = sg[t] - v; g_gcur[t] = sg[t] - v; }
        if (t == NG - 1) g_grow[NG] = sg[NG - 1];
    }
}

__global__ void scan_add_kernel() {
    int i = blockIdx.x * blockDim.x + threadIdx.x;
    if (i < NN) {
        int r = g_rowptr[i] + g_boffs[i >> 10];
        g_rowptr[i] = r;
        g_cursor[i] = r;
    }
}

__global__ void scatter_both_kernel() {
    int i = blockIdx.x * blockDim.x + threadIdx.x;
    if (i < NE) {
        int p = atomicAdd(&g_cursor[g_dst[i]], 1);
        g_col[p] = g_src[i];
    }
    if (i < NN) {
        int p = atomicAdd(&g_gcur[g_batch[i]], 1);
        g_glist[p] = i;
    }
}

// ---------------- conv1 input linears ----------------
__global__ void lin10_kernel(const float* __restrict__ x,
                             const float* __restrict__ sw_, const float* __restrict__ sb_,
                             const float* __restrict__ dw_, const float* __restrict__ db_,
                             float* __restrict__ m_out, float* __restrict__ xd_out) {
    __shared__ float sw[1000], dw[1000], sb[100], db[100];
    int t = threadIdx.x;
    for (int i = t; i < 1000; i += blockDim.x) { sw[i] = sw_[i]; dw[i] = dw_[i]; }
    for (int i = t; i < 100;  i += blockDim.x) { sb[i] = sb_[i]; db[i] = db_[i]; }
    __syncthreads();
    int id = blockIdx.x * blockDim.x + t;
    if (id >= NN * FD) return;
    int n = id / FD, f = id - n * FD;
    float xs[10];
#pragma unroll
    for (int k = 0; k < 10; k++) xs[k] = x[n * 10 + k];
    float a = sb[f], b = db[f];
#pragma unroll
    for (int k = 0; k < 10; k++) { a += xs[k] * sw[f * 10 + k]; b += xs[k] * dw[f * 10 + k]; }
    m_out[id]  = fmaxf(a, 0.0f) + 1e-7f;
    xd_out[id] = b;
}

// ---------------- softmax aggregation: ONLINE single-pass (1 exp/feature/edge) ----------------
// Warp per dst node; lane l (<25) owns features 4l..4l+3 (one float4 gather per edge).
template<bool TRANS>
__global__ void agg_kernel(const float* __restrict__ m, const float* __restrict__ xd,
                           float* __restrict__ out) {
    int w = (blockIdx.x * blockDim.x + threadIdx.x) >> 5;
    if (w >= NN) return;
    int lane = threadIdx.x & 31;
    if (lane >= 25) return;

    int beg = g_rowptr[w], end = g_rowptr[w + 1];
    float4 mx = make_float4(0.f, 0.f, 0.f, 0.f);
    float4 d  = make_float4(0.f, 0.f, 0.f, 0.f);
    float4 n  = make_float4(0.f, 0.f, 0.f, 0.f);
    int s_next = (beg < end) ? __ldg(&g_col[beg]) : 0;
    for (int i = beg; i < end; i++) {
        int s = s_next;
        if (i + 1 < end) s_next = __ldg(&g_col[i + 1]);
        float4 v = __ldg((const float4*)(m + (size_t)s * FD) + lane);
        if (TRANS) {
            v.x = fmaxf(v.x, 0.f) + 1e-7f; v.y = fmaxf(v.y, 0.f) + 1e-7f;
            v.z = fmaxf(v.z, 0.f) + 1e-7f; v.w = fmaxf(v.w, 0.f) + 1e-7f;
        }
        onl(v.x, mx.x, d.x, n.x);
        onl(v.y, mx.y, d.y, n.y);
        onl(v.z, mx.z, d.z, n.z);
        onl(v.w, mx.w, d.w, n.w);
    }
    float4 xv = __ldg((const float4*)(xd + (size_t)w * FD) + lane);
    float4 o;
    o.x = n.x / (d.x + 1e-16f) + xv.x;
    o.y = n.y / (d.y + 1e-16f) + xv.y;
    o.z = n.z / (d.z + 1e-16f) + xv.z;
    o.w = n.w / (d.w + 1e-16f) + xv.w;
    *((float4*)(out + (size_t)w * FD) + lane) = o;
}

// ============ persistent fp32 f32x2 GEMM: C[M, NOUT] = A[M,K] @ W[NOUT,K]^T ============
// Whole W panel transposed in smem as Wt[k][c] (f32x2 pairs read directly as ulonglong2).
// A tile (64 rows) staged transposed AsT[k][r] (stride 68; broadcast compute reads).
// Thread (tid<200): rowg=tid/25 (8 rows), colg=tid%25 (CPT cols) -> 8*CPT/2 FMA2 per k.
// EPI 0: relu((acc+bias)*gamma*rsqrt(1+1e-5)+beta)   EPI 1: relu(acc+bias)
template<int NOUT, int K, int CPT, int EPI>
__global__ __launch_bounds__(256, 1) void f2_gemm_kernel(
    const float* __restrict__ A, const float* __restrict__ W,
    const float* __restrict__ bias, const float* __restrict__ gamma,
    const float* __restrict__ beta, float* __restrict__ O) {

    constexpr int NPAIR = CPT / 2;
    constexpr int KQ = K / 4;
    constexpr int AS = 68;                 // AsT row stride (floats): 16B-aligned per k

    extern __shared__ float sf[];
    float* p_b = sf;
    float* p_s = p_b + NOUT;
    float* p_e = p_s + NOUT;
    float* Wt  = p_e + NOUT;               // [K][NOUT]
    float* AsT = Wt + K * NOUT;            // [K][AS]

    const int tid = threadIdx.x;
    const int rowg = tid / 25, colg = tid % 25;

    const float rs = rsqrtf(1.0f + 1e-5f);
    for (int i = tid; i < NOUT; i += 256) {
        p_b[i] = bias[i];
        if (EPI == 0) { p_s[i] = gamma[i] * rs; p_e[i] = beta[i]; }
    }
    // W panel -> smem transposed (once per CTA)
    for (int u = tid; u < NOUT * KQ; u += 256) {
        int c = u / KQ, kq = u - c * KQ;
        float4 wv = *(const float4*)(W + (size_t)c * K + kq * 4);
        Wt[(4 * kq + 0) * NOUT + c] = wv.x;
        Wt[(4 * kq + 1) * NOUT + c] = wv.y;
        Wt[(4 * kq + 2) * NOUT + c] = wv.z;
        Wt[(4 * kq + 3) * NOUT + c] = wv.w;
    }
    __syncthreads();

    const int NT = (NN + 63) / 64;
    for (int tile = blockIdx.x; tile < NT; tile += gridDim.x) {
        const int row0 = tile * 64;
        // stage A tile transposed (kq-major -> conflict-free STS)
        for (int u = tid; u < 64 * KQ; u += 256) {
            int r = u & 63, kq = u >> 6;
            int gr = row0 + r;
            float4 av = make_float4(0.f, 0.f, 0.f, 0.f);
            if (gr < NN) av = *(const float4*)(A + (size_t)gr * K + kq * 4);
            AsT[(4 * kq + 0) * AS + r] = av.x;
            AsT[(4 * kq + 1) * AS + r] = av.y;
            AsT[(4 * kq + 2) * AS + r] = av.z;
            AsT[(4 * kq + 3) * AS + r] = av.w;
        }
        __syncthreads();

        if (tid < 200) {
            unsigned long long acc[8][NPAIR];
#pragma unroll
            for (int i = 0; i < 8; i++)
#pragma unroll
                for (int p = 0; p < NPAIR; p++) acc[i][p] = 0ULL;

#pragma unroll 2
            for (int k = 0; k < K; k++) {
                const float* wr = Wt + k * NOUT + colg * CPT;
                unsigned long long bp[NPAIR];
                {
                    ulonglong2 t0 = *(const ulonglong2*)wr;
                    bp[0] = t0.x; bp[1] = t0.y;
                    if (NPAIR == 4) {
                        ulonglong2 t1 = *((const ulonglong2*)wr + 1);
                        bp[2] = t1.x; bp[3] = t1.y;
                    }
                }
                const float* ar = AsT + k * AS + rowg * 8;
                float4 a0 = *(const float4*)ar;
                float4 a1 = *(const float4*)(ar + 4);
                unsigned long long ad[8];
                PK2(ad[0], a0.x); PK2(ad[1], a0.y); PK2(ad[2], a0.z); PK2(ad[3], a0.w);
                PK2(ad[4], a1.x); PK2(ad[5], a1.y); PK2(ad[6], a1.z); PK2(ad[7], a1.w);
#pragma unroll
                for (int i = 0; i < 8; i++)
#pragma unroll
                    for (int p = 0; p < NPAIR; p++)
                        FMA2(acc[i][p], ad[i], bp[p]);
            }

            // epilogue
            const int c0 = colg * CPT;
#pragma unroll
            for (int i = 0; i < 8; i++) {
                int r = row0 + rowg * 8 + i;
                if (r < NN) {
                    float v[CPT];
#pragma unroll
                    for (int p = 0; p < NPAIR; p++) {
                        float lo, hi;
                        UPK2(lo, hi, acc[i][p]);
                        int c = c0 + 2 * p;
                        if (EPI == 0) {
                            v[2 * p]     = fmaxf((lo + p_b[c])     * p_s[c]     + p_e[c],     0.f);
                            v[2 * p + 1] = fmaxf((hi + p_b[c + 1]) * p_s[c + 1] + p_e[c + 1], 0.f);
                        } else {
                            v[2 * p]     = fmaxf(lo + p_b[c],     0.f);
                            v[2 * p + 1] = fmaxf(hi + p_b[c + 1], 0.f);
                        }
                    }
                    float* po = O + (size_t)r * NOUT + c0;
                    *(float4*)po = make_float4(v[0], v[1], v[2], v[3]);
                    if (CPT == 8)
                        *(float4*)(po + 4) = make_float4(v[4], v[5], v[6], v[7]);
                }
            }
        }
        __syncthreads();
    }
}

// ---------------- readout: block per graph, atomic-free segment sum/max ----------------
__global__ void readout_seg_kernel(const float* __restrict__ h, float* __restrict__ encode) {
    int g = blockIdx.x, t = threadIdx.x;
    if (t >= 100) return;
    int beg = g_grow[g], end = g_grow[g + 1];
    float s = 0.f, mx = 0.f;
    int i = beg;
    for (; i + 3 < end; i += 4) {
        int n0 = g_glist[i], n1 = g_glist[i + 1], n2 = g_glist[i + 2], n3 = g_glist[i + 3];
        float v0 = __ldg(&h[(size_t)n0 * FD + t]);
        float v1 = __ldg(&h[(size_t)n1 * FD + t]);
        float v2 = __ldg(&h[(size_t)n2 * FD + t]);
        float v3 = __ldg(&h[(size_t)n3 * FD + t]);
        s += v0 + v1 + v2 + v3;
        mx = fmaxf(mx, fmaxf(fmaxf(v0, v1), fmaxf(v2, v3)));
    }
    for (; i < end; i++) {
        float v = __ldg(&h[(size_t)g_glist[i] * FD + t]);
        s += v; mx = fmaxf(mx, v);
    }
    float cnt = (float)(end - beg);
    float mean = s / fmaxf(cnt, 1.0f);
    encode[g * FD2 + t]      += fmaxf(mean, 0.f);
    encode[g * FD2 + FD + t] += fmaxf(mx,   0.f);
}

// ---------------- head ----------------
__global__ void head_kernel(const float* __restrict__ encode,
                            const float* __restrict__ fc1_w, const float* __restrict__ fc1_b,
                            const float* __restrict__ cls_w, const float* __restrict__ cls_b,
                            float* __restrict__ logits) {
    __shared__ float enc[200];
    __shared__ float z[100];
    int g = blockIdx.x, t = threadIdx.x;
    for (int i = t; i < 200; i += 128) enc[i] = encode[g * 200 + i];
    __syncthreads();
    if (t < 100) {
        float a = fc1_b[t];
#pragma unroll 4
        for (int k = 0; k < 200; k++) a += enc[k] * __ldg(&fc1_w[t * 200 + k]);
        z[t] = fmaxf(a, 0.f);
    }
    __syncthreads();
    if (t < 64) {
        int o = t >> 5, lane = t & 31;
        float s = 0.f;
        for (int j = lane; j < 100; j += 32) s += z[j] * __ldg(&cls_w[o * 100 + j]);
#pragma unroll
        for (int off = 16; off; off >>= 1) s += __shfl_down_sync(0xffffffffu, s, off);
        if (lane == 0) logits[g * 2 + o] = s + cls_b[o];
    }
}

// ---------------- launch ----------------
extern "C" void kernel_launch(void* const* d_in, const int* in_sizes, int n_in,
                              void* d_out, int out_size) {
    const float* x       = (const float*)d_in[0];
    const void*  ei      = d_in[1];
    const void*  bt      = d_in[2];
    const float* c1_src_w = (const float*)d_in[3];
    const float* c1_src_b = (const float*)d_in[4];
    const float* c1_dst_w = (const float*)d_in[5];
    const float* c1_dst_b = (const float*)d_in[6];
    const float* cw1[3] = { (const float*)d_in[7],  (const float*)d_in[13], (const float*)d_in[19] };
    const float* cb1[3] = { (const float*)d_in[8],  (const float*)d_in[14], (const float*)d_in[20] };
    const float* cg [3] = { (const float*)d_in[9],  (const float*)d_in[15], (const float*)d_in[21] };
    const float* cbe[3] = { (const float*)d_in[10], (const float*)d_in[16], (const float*)d_in[22] };
    const float* cw2[3] = { (const float*)d_in[11], (const float*)d_in[17], (const float*)d_in[23] };
    const float* cb2[3] = { (const float*)d_in[12], (const float*)d_in[18], (const float*)d_in[24] };
    const float* fc1_w = (const float*)d_in[25];
    const float* fc1_b = (const float*)d_in[26];
    const float* cls_w = (const float*)d_in[27];
    const float* cls_b = (const float*)d_in[28];

    float* out    = (float*)d_out;
    float* logits = out;
    float* encode = out + NG * 2;

    float *pm, *pxd, *pout, *phh, *ph;
    cudaGetSymbolAddress((void**)&pm,   g_m);
    cudaGetSymbolAddress((void**)&pxd,  g_xd);
    cudaGetSymbolAddress((void**)&pout, g_out);
    cudaGetSymbolAddress((void**)&phh,  g_hh);
    cudaGetSymbolAddress((void**)&ph,   g_h);

    // smem: G1 = 3*200*4 + 100*200*4 + 100*68*4 = 109600 ; G2 = 3*100*4 + 200*100*4 + 200*68*4 = 135600
    const int SM1 = 3 * 200 * 4 + 100 * 200 * 4 + 100 * 68 * 4;
    const int SM2 = 3 * 100 * 4 + 200 * 100 * 4 + 200 * 68 * 4;
    cudaFuncSetAttribute(f2_gemm_kernel<200, 100, 8, 0>,
                         cudaFuncAttributeMaxDynamicSharedMemorySize, SM1);
    cudaFuncSetAttribute(f2_gemm_kernel<100, 200, 4, 1>,
                         cudaFuncAttributeMaxDynamicSharedMemorySize, SM2);

    const int TB = 256;
    const int GE  = (NE + TB - 1) / TB;
    const int GNF = (NN * FD + TB - 1) / TB;
    const int NB_SCAN = (NN + 1023) / 1024;
    const int GEMM_GRID = 148;

    // CSR build (dst identical across convs -> build once) + batch CSR for readout
    detect_kernel<<<1, 1024>>>((const unsigned long long*)ei);
    prep_kernel<<<GE, TB>>>(ei, bt, out);
    hist_kernel<<<GE, TB>>>();
    scan_block_kernel<<<NB_SCAN, 1024>>>();
    scan_misc_kernel<<<2, 1024>>>(NB_SCAN);
    scan_add_kernel<<<(NN + TB - 1) / TB, TB>>>();
    scatter_both_kernel<<<GE, TB>>>();

    // ---- conv1 ----
    lin10_kernel<<<GNF, TB>>>(x, c1_src_w, c1_src_b, c1_dst_w, c1_dst_b, pm, pxd);
    agg_kernel<false><<<(NN * 32 + TB - 1) / TB, TB>>>(pm, pxd, pout);
    f2_gemm_kernel<200, 100, 8, 0><<<GEMM_GRID, 256, SM1>>>(
        pout, cw1[0], cb1[0], cg[0], cbe[0], phh);
    f2_gemm_kernel<100, 200, 4, 1><<<GEMM_GRID, 256, SM2>>>(
        phh, cw2[0], cb2[0], nullptr, nullptr, ph);
    readout_seg_kernel<<<NG, 128>>>(ph, encode);

    // ---- conv2 / conv3 ----
    for (int c = 1; c < 3; c++) {
        agg_kernel<true><<<(NN * 32 + TB - 1) / TB, TB>>>(ph, ph, pout);
        f2_gemm_kernel<200, 100, 8, 0><<<GEMM_GRID, 256, SM1>>>(
            pout, cw1[c], cb1[c], cg[c], cbe[c], phh);
        f2_gemm_kernel<100, 200, 4, 1><<<GEMM_GRID, 256, SM2>>>(
            phh, cw2[c], cb2[c], nullptr, nullptr, ph);
        readout_seg_kernel<<<NG, 128>>>(ph, encode);
    }

    head_kernel<<<NG, 128>>>(encode, fc1_w, fc1_b, cls_w, cls_b, logits);
}

// round 16
// speedup vs baseline: 1.0023x; 1.0023x over previous
#include <cuda_runtime.h>
#include <cstdint>

#define NN 100000
#define NE 1600000
#define NG 512
#define FD 100
#define FD2 200
#define OUTSZ (NG*2 + NG*200)

// ---------------- scratch (device globals; no allocation allowed) ----------------
__device__ float g_m [NN*FD];
__device__ float g_xd[NN*FD];
__device__ float g_out[NN*FD];    // agg output (GEMM1 input)
__device__ float g_hh[NN*FD2];    // MLP hidden (GEMM2 input)
__device__ float g_h [NN*FD];     // conv output
__device__ int   g_src[NE];
__device__ int   g_dst[NE];
__device__ int   g_col[NE];
__device__ int   g_rowptr[NN+1];
__device__ int   g_cursor[NN];
__device__ int   g_counts[NN];
__device__ int   g_batch[NN];
__device__ int   g_bsums[128];
__device__ int   g_boffs[128];
__device__ int   g_gcnt[NG];
__device__ int   g_grow[NG+1];
__device__ int   g_gcur[NG];
__device__ int   g_glist[NN];
__device__ int   g_is64;

// ================= f32x2 helpers (PTX ISA 8.6+, sm_100 family incl. sm_103) =================
#define FMA2(acc, a, b) \
    asm("fma.rn.f32x2 %0, %1, %2, %0;" : "+l"(acc) : "l"(a), "l"(b))
#define PK2(d, x) \
    asm("mov.b64 %0, {%1, %1};" : "=l"(d) : "f"(x))
#define UPK2(lo, hi, v) \
    asm("mov.b64 {%0, %1}, %2;" : "=f"(lo), "=f"(hi) : "l"(v))

// online softmax update, ONE exp per call: e = exp(-|v-mx|)
__device__ __forceinline__ void onl(float v, float& mx, float& d, float& n) {
    float t = v - mx;
    float e = __expf(-fabsf(t));
    if (t <= 0.f) {
        d += e;
        n += e * v;
    } else {
        d = d * e + 1.f;
        n = n * e + v;
        mx = v;
    }
}

// ---------------- dtype sniff ----------------
__global__ void detect_kernel(const unsigned long long* __restrict__ ei) {
    __shared__ int found;
    if (threadIdx.x == 0) found = 0;
    __syncthreads();
    unsigned long long v = ei[threadIdx.x];
    if ((v >> 32) != 0ULL) found = 1;
    __syncthreads();
    if (threadIdx.x == 0) g_is64 = found ? 0 : 1;
}

__global__ void prep_kernel(const void* __restrict__ ei, const void* __restrict__ bt,
                            float* __restrict__ out) {
    int i = blockIdx.x * blockDim.x + threadIdx.x;
    int is64 = g_is64;
    if (i < NE) {
        if (is64) {
            const long long* e = (const long long*)ei;
            g_src[i] = (int)e[i];
            g_dst[i] = (int)e[NE + i];
        } else {
            const int* e = (const int*)ei;
            g_src[i] = e[i];
            g_dst[i] = e[NE + i];
        }
    }
    if (i < NN) {
        if (is64) g_batch[i] = (int)((const long long*)bt)[i];
        else      g_batch[i] = ((const int*)bt)[i];
        g_counts[i] = 0;
    }
    if (i < NG)    g_gcnt[i] = 0;
    if (i < OUTSZ) out[i] = 0.0f;
}

__global__ void hist_kernel() {
    int i = blockIdx.x * blockDim.x + threadIdx.x;
    if (i < NE) atomicAdd(&g_counts[g_dst[i]], 1);
    if (i < NN) atomicAdd(&g_gcnt[g_batch[i]], 1);
}

__global__ void scan_block_kernel() {
    __shared__ int sh[1024];
    int t = threadIdx.x;
    int i = blockIdx.x * 1024 + t;
    int v = (i < NN) ? g_counts[i] : 0;
    sh[t] = v;
    __syncthreads();
    for (int off = 1; off < 1024; off <<= 1) {
        int tmp = (t >= off) ? sh[t - off] : 0;
        __syncthreads();
        sh[t] += tmp;
        __syncthreads();
    }
    if (i < NN) g_rowptr[i] = sh[t] - v;
    if (t == 1023) g_bsums[blockIdx.x] = sh[1023];
}

__global__ void scan_misc_kernel(int nb) {
    __shared__ int sg[NG];
    int t = threadIdx.x;
    if (blockIdx.x == 0) {
        if (t == 0) {
            int run = 0;
            for (int i = 0; i < nb; i++) { g_boffs[i] = run; run += g_bsums[i]; }
            g_rowptr[NN] = run;
        }
    } else {
        int v = (t < NG) ? g_gcnt[t] : 0;
        if (t < NG) sg[t] = v;
        __syncthreads();
        for (int off = 1; off < NG; off <<= 1) {
            int tmp = (t < NG && t >= off) ? sg[t - off] : 0;
            __syncthreads();
            if (t < NG) sg[t] += tmp;
            __syncthreads();
        }
        if (t < NG) { g_grow[t] = sg[t] - v; g_gcur[t] = sg[t] - v; }
        if (t == NG - 1) g_grow[NG] = sg[NG - 1];
    }
}

__global__ void scan_add_kernel() {
    int i = blockIdx.x * blockDim.x + threadIdx.x;
    if (i < NN) {
        int r = g_rowptr[i] + g_boffs[i >> 10];
        g_rowptr[i] = r;
        g_cursor[i] = r;
    }
}

__global__ void scatter_both_kernel() {
    int i = blockIdx.x * blockDim.x + threadIdx.x;
    if (i < NE) {
        int p = atomicAdd(&g_cursor[g_dst[i]], 1);
        g_col[p] = g_src[i];
    }
    if (i < NN) {
        int p = atomicAdd(&g_gcur[g_batch[i]], 1);
        g_glist[p] = i;
    }
}

// ---------------- conv1 input linears ----------------
__global__ void lin10_kernel(const float* __restrict__ x,
                             const float* __restrict__ sw_, const float* __restrict__ sb_,
                             const float* __restrict__ dw_, const float* __restrict__ db_,
                             float* __restrict__ m_out, float* __restrict__ xd_out) {
    __shared__ float sw[1000], dw[1000], sb[100], db[100];
    int t = threadIdx.x;
    for (int i = t; i < 1000; i += blockDim.x) { sw[i] = sw_[i]; dw[i] = dw_[i]; }
    for (int i = t; i < 100;  i += blockDim.x) { sb[i] = sb_[i]; db[i] = db_[i]; }
    __syncthreads();
    int id = blockIdx.x * blockDim.x + t;
    if (id >= NN * FD) return;
    int n = id / FD, f = id - n * FD;
    float xs[10];
#pragma unroll
    for (int k = 0; k < 10; k++) xs[k] = x[n * 10 + k];
    float a = sb[f], b = db[f];
#pragma unroll
    for (int k = 0; k < 10; k++) { a += xs[k] * sw[f * 10 + k]; b += xs[k] * dw[f * 10 + k]; }
    m_out[id]  = fmaxf(a, 0.0f) + 1e-7f;
    xd_out[id] = b;
}

// ---------------- softmax aggregation: ONLINE single-pass (1 exp/feature/edge) ----------------
// Warp per dst node; lane l (<25) owns features 4l..4l+3 (one float4 gather per edge).
template<bool TRANS>
__global__ void agg_kernel(const float* __restrict__ m, const float* __restrict__ xd,
                           float* __restrict__ out) {
    int w = (blockIdx.x * blockDim.x + threadIdx.x) >> 5;
    if (w >= NN) return;
    int lane = threadIdx.x & 31;
    if (lane >= 25) return;

    int beg = g_rowptr[w], end = g_rowptr[w + 1];
    float4 mx = make_float4(0.f, 0.f, 0.f, 0.f);
    float4 d  = make_float4(0.f, 0.f, 0.f, 0.f);
    float4 n  = make_float4(0.f, 0.f, 0.f, 0.f);
    int s_next = (beg < end) ? __ldg(&g_col[beg]) : 0;
    for (int i = beg; i < end; i++) {
        int s = s_next;
        if (i + 1 < end) s_next = __ldg(&g_col[i + 1]);
        float4 v = __ldg((const float4*)(m + (size_t)s * FD) + lane);
        if (TRANS) {
            v.x = fmaxf(v.x, 0.f) + 1e-7f; v.y = fmaxf(v.y, 0.f) + 1e-7f;
            v.z = fmaxf(v.z, 0.f) + 1e-7f; v.w = fmaxf(v.w, 0.f) + 1e-7f;
        }
        onl(v.x, mx.x, d.x, n.x);
        onl(v.y, mx.y, d.y, n.y);
        onl(v.z, mx.z, d.z, n.z);
        onl(v.w, mx.w, d.w, n.w);
    }
    float4 xv = __ldg((const float4*)(xd + (size_t)w * FD) + lane);
    float4 o;
    o.x = n.x / (d.x + 1e-16f) + xv.x;
    o.y = n.y / (d.y + 1e-16f) + xv.y;
    o.z = n.z / (d.z + 1e-16f) + xv.z;
    o.w = n.w / (d.w + 1e-16f) + xv.w;
    *((float4*)(out + (size_t)w * FD) + lane) = o;
}

// ============ persistent fp32 f32x2 GEMM: C[M, NOUT] = A[M,K] @ W[NOUT,K]^T ============
// Whole W panel transposed in smem as Wt[k][c] (f32x2 pairs read directly as ulonglong2).
// A tile (64 rows) staged transposed AsT[k][r] (stride 68; broadcast compute reads).
// Thread (tid<200): rowg=tid/25 (8 rows), colg=tid%25 (CPT cols) -> 8*CPT/2 FMA2 per k.
// EPI 0: relu((acc+bias)*gamma*rsqrt(1+1e-5)+beta)   EPI 1: relu(acc+bias)
template<int NOUT, int K, int CPT, int EPI>
__global__ __launch_bounds__(256, 1) void f2_gemm_kernel(
    const float* __restrict__ A, const float* __restrict__ W,
    const float* __restrict__ bias, const float* __restrict__ gamma,
    const float* __restrict__ beta, float* __restrict__ O) {

    constexpr int NPAIR = CPT / 2;
    constexpr int KQ = K / 4;
    constexpr int AS = 68;                 // AsT row stride (floats): 16B-aligned per k

    extern __shared__ float sf[];
    float* p_b = sf;
    float* p_s = p_b + NOUT;
    float* p_e = p_s + NOUT;
    float* Wt  = p_e + NOUT;               // [K][NOUT]
    float* AsT = Wt + K * NOUT;            // [K][AS]

    const int tid = threadIdx.x;
    const int rowg = tid / 25, colg = tid % 25;

    const float rs = rsqrtf(1.0f + 1e-5f);
    for (int i = tid; i < NOUT; i += 256) {
        p_b[i] = bias[i];
        if (EPI == 0) { p_s[i] = gamma[i] * rs; p_e[i] = beta[i]; }
    }
    // W panel -> smem transposed (once per CTA)
    for (int u = tid; u < NOUT * KQ; u += 256) {
        int c = u / KQ, kq = u - c * KQ;
        float4 wv = *(const float4*)(W + (size_t)c * K + kq * 4);
        Wt[(4 * kq + 0) * NOUT + c] = wv.x;
        Wt[(4 * kq + 1) * NOUT + c] = wv.y;
        Wt[(4 * kq + 2) * NOUT + c] = wv.z;
        Wt[(4 * kq + 3) * NOUT + c] = wv.w;
    }
    __syncthreads();

    const int NT = (NN + 63) / 64;
    for (int tile = blockIdx.x; tile < NT; tile += gridDim.x) {
        const int row0 = tile * 64;
        // stage A tile transposed (kq-major -> conflict-free STS)
        for (int u = tid; u < 64 * KQ; u += 256) {
            int r = u & 63, kq = u >> 6;
            int gr = row0 + r;
            float4 av = make_float4(0.f, 0.f, 0.f, 0.f);
            if (gr < NN) av = *(const float4*)(A + (size_t)gr * K + kq * 4);
            AsT[(4 * kq + 0) * AS + r] = av.x;
            AsT[(4 * kq + 1) * AS + r] = av.y;
            AsT[(4 * kq + 2) * AS + r] = av.z;
            AsT[(4 * kq + 3) * AS + r] = av.w;
        }
        __syncthreads();

        if (tid < 200) {
            unsigned long long acc[8][NPAIR];
#pragma unroll
            for (int i = 0; i < 8; i++)
#pragma unroll
                for (int p = 0; p < NPAIR; p++) acc[i][p] = 0ULL;

#pragma unroll 2
            for (int k = 0; k < K; k++) {
                const float* wr = Wt + k * NOUT + colg * CPT;
                unsigned long long bp[NPAIR];
                {
                    ulonglong2 t0 = *(const ulonglong2*)wr;
                    bp[0] = t0.x; bp[1] = t0.y;
                    if (NPAIR == 4) {
                        ulonglong2 t1 = *((const ulonglong2*)wr + 1);
                        bp[2] = t1.x; bp[3] = t1.y;
                    }
                }
                const float* ar = AsT + k * AS + rowg * 8;
                float4 a0 = *(const float4*)ar;
                float4 a1 = *(const float4*)(ar + 4);
                unsigned long long ad[8];
                PK2(ad[0], a0.x); PK2(ad[1], a0.y); PK2(ad[2], a0.z); PK2(ad[3], a0.w);
                PK2(ad[4], a1.x); PK2(ad[5], a1.y); PK2(ad[6], a1.z); PK2(ad[7], a1.w);
#pragma unroll
                for (int i = 0; i < 8; i++)
#pragma unroll
                    for (int p = 0; p < NPAIR; p++)
                        FMA2(acc[i][p], ad[i], bp[p]);
            }

            // epilogue
            const int c0 = colg * CPT;
#pragma unroll
            for (int i = 0; i < 8; i++) {
                int r = row0 + rowg * 8 + i;
                if (r < NN) {
                    float v[CPT];
#pragma unroll
                    for (int p = 0; p < NPAIR; p++) {
                        float lo, hi;
                        UPK2(lo, hi, acc[i][p]);
                        int c = c0 + 2 * p;
                        if (EPI == 0) {
                            v[2 * p]     = fmaxf((lo + p_b[c])     * p_s[c]     + p_e[c],     0.f);
                            v[2 * p + 1] = fmaxf((hi + p_b[c + 1]) * p_s[c + 1] + p_e[c + 1], 0.f);
                        } else {
                            v[2 * p]     = fmaxf(lo + p_b[c],     0.f);
                            v[2 * p + 1] = fmaxf(hi + p_b[c + 1], 0.f);
                        }
                    }
                    float* po = O + (size_t)r * NOUT + c0;
                    *(float4*)po = make_float4(v[0], v[1], v[2], v[3]);
                    if (CPT == 8)
                        *(float4*)(po + 4) = make_float4(v[4], v[5], v[6], v[7]);
                }
            }
        }
        __syncthreads();
    }
}

// ---------------- readout: block per graph, atomic-free segment sum/max ----------------
__global__ void readout_seg_kernel(const float* __restrict__ h, float* __restrict__ encode) {
    int g = blockIdx.x, t = threadIdx.x;
    if (t >= 100) return;
    int beg = g_grow[g], end = g_grow[g + 1];
    float s = 0.f, mx = 0.f;
    int i = beg;
    for (; i + 3 < end; i += 4) {
        int n0 = g_glist[i], n1 = g_glist[i + 1], n2 = g_glist[i + 2], n3 = g_glist[i + 3];
        float v0 = __ldg(&h[(size_t)n0 * FD + t]);
        float v1 = __ldg(&h[(size_t)n1 * FD + t]);
        float v2 = __ldg(&h[(size_t)n2 * FD + t]);
        float v3 = __ldg(&h[(size_t)n3 * FD + t]);
        s += v0 + v1 + v2 + v3;
        mx = fmaxf(mx, fmaxf(fmaxf(v0, v1), fmaxf(v2, v3)));
    }
    for (; i < end; i++) {
        float v = __ldg(&h[(size_t)g_glist[i] * FD + t]);
        s += v; mx = fmaxf(mx, v);
    }
    float cnt = (float)(end - beg);
    float mean = s / fmaxf(cnt, 1.0f);
    encode[g * FD2 + t]      += fmaxf(mean, 0.f);
    encode[g * FD2 + FD + t] += fmaxf(mx,   0.f);
}

// ---------------- head ----------------
__global__ void head_kernel(const float* __restrict__ encode,
                            const float* __restrict__ fc1_w, const float* __restrict__ fc1_b,
                            const float* __restrict__ cls_w, const float* __restrict__ cls_b,
                            float* __restrict__ logits) {
    __shared__ float enc[200];
    __shared__ float z[100];
    int g = blockIdx.x, t = threadIdx.x;
    for (int i = t; i < 200; i += 128) enc[i] = encode[g * 200 + i];
    __syncthreads();
    if (t < 100) {
        float a = fc1_b[t];
#pragma unroll 4
        for (int k = 0; k < 200; k++) a += enc[k] * __ldg(&fc1_w[t * 200 + k]);
        z[t] = fmaxf(a, 0.f);
    }
    __syncthreads();
    if (t < 64) {
        int o = t >> 5, lane = t & 31;
        float s = 0.f;
        for (int j = lane; j < 100; j += 32) s += z[j] * __ldg(&cls_w[o * 100 + j]);
#pragma unroll
        for (int off = 16; off; off >>= 1) s += __shfl_down_sync(0xffffffffu, s, off);
        if (lane == 0) logits[g * 2 + o] = s + cls_b[o];
    }
}

// ---------------- launch ----------------
extern "C" void kernel_launch(void* const* d_in, const int* in_sizes, int n_in,
                              void* d_out, int out_size) {
    const float* x       = (const float*)d_in[0];
    const void*  ei      = d_in[1];
    const void*  bt      = d_in[2];
    const float* c1_src_w = (const float*)d_in[3];
    const float* c1_src_b = (const float*)d_in[4];
    const float* c1_dst_w = (const float*)d_in[5];
    const float* c1_dst_b = (const float*)d_in[6];
    const float* cw1[3] = { (const float*)d_in[7],  (const float*)d_in[13], (const float*)d_in[19] };
    const float* cb1[3] = { (const float*)d_in[8],  (const float*)d_in[14], (const float*)d_in[20] };
    const float* cg [3] = { (const float*)d_in[9],  (const float*)d_in[15], (const float*)d_in[21] };
    const float* cbe[3] = { (const float*)d_in[10], (const float*)d_in[16], (const float*)d_in[22] };
    const float* cw2[3] = { (const float*)d_in[11], (const float*)d_in[17], (const float*)d_in[23] };
    const float* cb2[3] = { (const float*)d_in[12], (const float*)d_in[18], (const float*)d_in[24] };
    const float* fc1_w = (const float*)d_in[25];
    const float* fc1_b = (const float*)d_in[26];
    const float* cls_w = (const float*)d_in[27];
    const float* cls_b = (const float*)d_in[28];

    float* out    = (float*)d_out;
    float* logits = out;
    float* encode = out + NG * 2;

    float *pm, *pxd, *pout, *phh, *ph;
    cudaGetSymbolAddress((void**)&pm,   g_m);
    cudaGetSymbolAddress((void**)&pxd,  g_xd);
    cudaGetSymbolAddress((void**)&pout, g_out);
    cudaGetSymbolAddress((void**)&phh,  g_hh);
    cudaGetSymbolAddress((void**)&ph,   g_h);

    // smem: G1 = 3*200*4 + 100*200*4 + 100*68*4 = 109600 ; G2 = 3*100*4 + 200*100*4 + 200*68*4 = 135600
    const int SM1 = 3 * 200 * 4 + 100 * 200 * 4 + 100 * 68 * 4;
    const int SM2 = 3 * 100 * 4 + 200 * 100 * 4 + 200 * 68 * 4;
    cudaFuncSetAttribute(f2_gemm_kernel<200, 100, 8, 0>,
                         cudaFuncAttributeMaxDynamicSharedMemorySize, SM1);
    cudaFuncSetAttribute(f2_gemm_kernel<100, 200, 4, 1>,
                         cudaFuncAttributeMaxDynamicSharedMemorySize, SM2);

    const int TB = 256;
    const int GE  = (NE + TB - 1) / TB;
    const int GNF = (NN * FD + TB - 1) / TB;
    const int NB_SCAN = (NN + 1023) / 1024;
    const int GEMM_GRID = 148;

    // CSR build (dst identical across convs -> build once) + batch CSR for readout
    detect_kernel<<<1, 1024>>>((const unsigned long long*)ei);
    prep_kernel<<<GE, TB>>>(ei, bt, out);
    hist_kernel<<<GE, TB>>>();
    scan_block_kernel<<<NB_SCAN, 1024>>>();
    scan_misc_kernel<<<2, 1024>>>(NB_SCAN);
    scan_add_kernel<<<(NN + TB - 1) / TB, TB>>>();
    scatter_both_kernel<<<GE, TB>>>();

    // ---- conv1 ----
    lin10_kernel<<<GNF, TB>>>(x, c1_src_w, c1_src_b, c1_dst_w, c1_dst_b, pm, pxd);
    agg_kernel<false><<<(NN * 32 + TB - 1) / TB, TB>>>(pm, pxd, pout);
    f2_gemm_kernel<200, 100, 8, 0><<<GEMM_GRID, 256, SM1>>>(
        pout, cw1[0], cb1[0], cg[0], cbe[0], phh);
    f2_gemm_kernel<100, 200, 4, 1><<<GEMM_GRID, 256, SM2>>>(
        phh, cw2[0], cb2[0], nullptr, nullptr, ph);
    readout_seg_kernel<<<NG, 128>>>(ph, encode);

    // ---- conv2 / conv3 ----
    for (int c = 1; c < 3; c++) {
        agg_kernel<true><<<(NN * 32 + TB - 1) / TB, TB>>>(ph, ph, pout);
        f2_gemm_kernel<200, 100, 8, 0><<<GEMM_GRID, 256, SM1>>>(
            pout, cw1[c], cb1[c], cg[c], cbe[c], phh);
        f2_gemm_kernel<100, 200, 4, 1><<<GEMM_GRID, 256, SM2>>>(
            phh, cw2[c], cb2[c], nullptr, nullptr, ph);
        readout_seg_kernel<<<NG, 128>>>(ph, encode);
    }

    head_kernel<<<NG, 128>>>(encode, fc1_w, fc1_b, cls_w, cls_b, logits);
}